// round 8
// baseline (speedup 1.0000x reference)
#include <cuda_runtime.h>
#include <cuda_fp16.h>
#include <cstdint>
#include <cstddef>

#define B_  4
#define C_  256
#define CQ_ 32
#define N_  4096
#define JT  128             // j tile per CTA
#define IT  64              // i tile per mainloop step
#define NIT (N_ / IT)       // 64
#define NTHR 512            // 16 warps
#define KSCALE 0.09016844005556021f   // (1/16) * log2(e)

// ---------------- scratch (device globals: allocation-free, 10 MB) ---------
// d_f: [b][n][q] Wq (query) projection -- the softmax/contraction index i side
// d_g: [b][n][q] Wk (key)   projection -- the output index j side
__device__ __half d_f[(size_t)B_ * N_ * CQ_];
__device__ __half d_g[(size_t)B_ * N_ * CQ_];
__device__ __half d_v[(size_t)B_ * C_ * N_];    // [b][c][n] values

__device__ __forceinline__ float ex2f(float x) {
    float y; asm("ex2.approx.f32 %0, %1;" : "=f"(y) : "f"(x)); return y;
}
__device__ __forceinline__ void mma_f16(float* d, const uint32_t* a,
                                        const uint32_t* b) {
    asm volatile(
        "mma.sync.aligned.m16n8k16.row.col.f32.f16.f16.f32 "
        "{%0,%1,%2,%3}, {%4,%5,%6,%7}, {%8,%9}, {%0,%1,%2,%3};"
        : "+f"(d[0]), "+f"(d[1]), "+f"(d[2]), "+f"(d[3])
        : "r"(a[0]), "r"(a[1]), "r"(a[2]), "r"(a[3]), "r"(b[0]), "r"(b[1]));
}
__device__ __forceinline__ uint32_t packh2(float a, float b) {
    __half2 p = __floats2half2_rn(a, b);
    return *reinterpret_cast<uint32_t*>(&p);
}

// --------------------------- SMEM layout (bytes) ---------------------------
// g tile:   [128 j][32 q fp16], row stride 80 B (conflict-free frag loads)
// f tiles:  2 x [64 i][32 q fp16], row stride 80 B
// V tiles:  2 x [256 c][64 i fp16], row stride 144 B
// P tiles:  2 x [128 j][64 i fp16], row stride 144 B
#define GSTR 80
#define VSTR 144
#define FBUF 5120                        // 64*80
#define VBUF 36864                       // 256*144
#define PBUF 18432                       // 128*144
#define OFF_G    0                       // 10240
#define OFF_F    10240                   // 2 x 5120   -> 20480
#define OFF_V    20480                   // 2 x 36864  -> 94208
#define OFF_P    94208                   // 2 x 18432  -> 131072
#define OFF_LRED 131072                  // 16*16*4 = 1024
#define OFF_RINV 132096                  // 128*4
#define SMEM_TOTAL 132608

// =================== kernel 1a: f/g projection (fp32 FFMA) ================
// Y[b][n][q] (fp16, transposed) = W[q][c] @ x[b][c][n]
__global__ void proj_fg_kernel(const float* __restrict__ W,
                               const float* __restrict__ x, int which) {
    __half* Y = which ? d_g : d_f;
    const int b  = blockIdx.z;
    const int n0 = blockIdx.x * 128;
    const float* X = x + (size_t)b * C_ * N_;

    __shared__ float Ws[32][33];
    __shared__ float Xs[32][128];

    const int tid = threadIdx.x;
    const int r0 = (tid >> 5) << 2;
    const int c0 = (tid & 31) << 2;

    float acc[4][4] = {};
    for (int kk = 0; kk < C_; kk += 32) {
        #pragma unroll
        for (int it = 0; it < 4; ++it) {
            int e = tid + 256 * it;
            int r = e >> 5, cc = e & 31;
            Ws[r][cc] = W[(size_t)r * C_ + kk + cc];
        }
        #pragma unroll
        for (int it = 0; it < 4; ++it) {
            int e = tid + 256 * it;
            int r = e >> 5, c4 = (e & 31) << 2;
            *reinterpret_cast<float4*>(&Xs[r][c4]) =
                *reinterpret_cast<const float4*>(&X[(size_t)(kk + r) * N_ + n0 + c4]);
        }
        __syncthreads();
        #pragma unroll
        for (int k = 0; k < 32; ++k) {
            float4 xv = *reinterpret_cast<const float4*>(&Xs[k][c0]);
            #pragma unroll
            for (int i = 0; i < 4; ++i) {
                float w = Ws[r0 + i][k];
                acc[i][0] = fmaf(w, xv.x, acc[i][0]);
                acc[i][1] = fmaf(w, xv.y, acc[i][1]);
                acc[i][2] = fmaf(w, xv.z, acc[i][2]);
                acc[i][3] = fmaf(w, xv.w, acc[i][3]);
            }
        }
        __syncthreads();
    }
    #pragma unroll
    for (int k = 0; k < 4; ++k) {   // transposed fp16 write: [n][q]
        int n = n0 + c0 + k;
        uint2 w2 = make_uint2(packh2(acc[0][k], acc[1][k]),
                              packh2(acc[2][k], acc[3][k]));
        *reinterpret_cast<uint2*>(&Y[((size_t)b * N_ + n) * CQ_ + r0]) = w2;
    }
}

// =================== kernel 1b: v projection (fp32 FFMA) ==================
__global__ void proj_v_kernel(const float* __restrict__ W,
                              const float* __restrict__ x) {
    const int b  = blockIdx.z;
    const int n0 = blockIdx.x * 128;
    const int m0 = blockIdx.y * 32;
    const float* X = x + (size_t)b * C_ * N_;

    __shared__ float Ws[32][33];
    __shared__ float Xs[32][128];

    const int tid = threadIdx.x;
    const int r0 = (tid >> 5) << 2;
    const int c0 = (tid & 31) << 2;

    float acc[4][4] = {};
    for (int kk = 0; kk < C_; kk += 32) {
        #pragma unroll
        for (int it = 0; it < 4; ++it) {
            int e = tid + 256 * it;
            int r = e >> 5, cc = e & 31;
            Ws[r][cc] = W[(size_t)(m0 + r) * C_ + kk + cc];
        }
        #pragma unroll
        for (int it = 0; it < 4; ++it) {
            int e = tid + 256 * it;
            int r = e >> 5, c4 = (e & 31) << 2;
            *reinterpret_cast<float4*>(&Xs[r][c4]) =
                *reinterpret_cast<const float4*>(&X[(size_t)(kk + r) * N_ + n0 + c4]);
        }
        __syncthreads();
        #pragma unroll
        for (int k = 0; k < 32; ++k) {
            float4 xv = *reinterpret_cast<const float4*>(&Xs[k][c0]);
            #pragma unroll
            for (int i = 0; i < 4; ++i) {
                float w = Ws[r0 + i][k];
                acc[i][0] = fmaf(w, xv.x, acc[i][0]);
                acc[i][1] = fmaf(w, xv.y, acc[i][1]);
                acc[i][2] = fmaf(w, xv.z, acc[i][2]);
                acc[i][3] = fmaf(w, xv.w, acc[i][3]);
            }
        }
        __syncthreads();
    }
    #pragma unroll
    for (int i = 0; i < 4; ++i) {
        uint2 w2 = make_uint2(packh2(acc[i][0], acc[i][1]),
                              packh2(acc[i][2], acc[i][3]));
        *reinterpret_cast<uint2*>(&d_v[((size_t)b * C_ + m0 + r0 + i) * N_ + n0 + c0]) = w2;
    }
}

// ============ kernel 2: fused, single-barrier software pipeline ===========
// Per CTA: batch b, 128-j tile. 16 warps. i-tiles of 64, double-buffered.
// Iteration t (one __syncthreads at top):
//   loads:   V(t+1) -> vbuf (t+1)%2,  f(t+2) -> fbuf t%2
//   phase A(t+1): S(16j x 32i) = g.f  (warp pair per j strip), p=ex2 -> P (t+1)%2
//   phase B(t):   O(16c x 128j) += V(t) * P(t)   [reads bufs t%2]
// MUFU (ex2) + LDG latency hide under phase-B HMMAs (no barrier between).
__global__ void __launch_bounds__(NTHR, 1)
fused_attn_mma(float* __restrict__ out) {
    extern __shared__ __align__(16) char smem[];
    const int b  = blockIdx.y;
    const int jb = blockIdx.x * JT;
    const int tid  = threadIdx.x;
    const int lane = tid & 31, warp = tid >> 5;
    const int lr = lane >> 2, lm = lane & 3;
    const int jw = (warp >> 1) * 16;    // phase-A j strip (2 warps share)
    const int ih = warp & 1;            // phase-A i half (0: i 0-31, 1: 32-63)
    const int cw = warp * 16;           // phase-B c strip

    const __half* fB = d_f + (size_t)b * N_ * CQ_;
    const __half* gB = d_g + (size_t)b * N_ * CQ_;
    const __half* vB = d_v + (size_t)b * C_ * N_;

    // ---------------- prologue loads: g, f(0), f(1), V(0) ----------------
    {   // g: 128 rows x 4 uint4
        int row = tid >> 2, ch = tid & 3;
        uint4 w = *reinterpret_cast<const uint4*>(&gB[(size_t)(jb + row) * CQ_ + ch * 8]);
        *reinterpret_cast<uint4*>(smem + OFF_G + row * GSTR + ch * 16) = w;
    }
    {   // f(0) -> fbuf0 (tid<256), f(1) -> fbuf1 (tid>=256)
        int h = tid >> 8;                  // 0 or 1
        int id = tid & 255;                // 256 x 16B per buffer
        int row = id >> 2, ch = id & 3;
        uint4 w = *reinterpret_cast<const uint4*>(
            &fB[(size_t)(h * IT + row) * CQ_ + ch * 8]);
        *reinterpret_cast<uint4*>(smem + OFF_F + h * FBUF + row * GSTR + ch * 16) = w;
    }
    #pragma unroll
    for (int it = 0; it < 4; ++it) {       // V(0): 2048 x 16B -> vbuf0
        int id = tid + NTHR * it;
        int row = id >> 3, ch = id & 7;
        uint4 w = *reinterpret_cast<const uint4*>(&vB[(size_t)row * N_ + ch * 8]);
        *reinterpret_cast<uint4*>(smem + OFF_V + row * VSTR + ch * 16) = w;
    }

    float oacc[16][4];
    #pragma unroll
    for (int n = 0; n < 16; ++n)
        #pragma unroll
        for (int k = 0; k < 4; ++k) oacc[n][k] = 0.f;
    float lsum0 = 0.f, lsum1 = 0.f;

    __syncthreads();                       // prologue tiles visible

    // ---------------- prologue phase A(0): P(0) -> pbuf0 ----------------
    {
        float sacc[4][4] = {};
        #pragma unroll
        for (int kk = 0; kk < 2; ++kk) {
            uint32_t ag[4];
            const char* ga = smem + OFF_G + (jw + lr) * GSTR + kk * 32 + lm * 4;
            ag[0] = *(const uint32_t*)ga;
            ag[1] = *(const uint32_t*)(ga + 8 * GSTR);
            ag[2] = *(const uint32_t*)(ga + 16);
            ag[3] = *(const uint32_t*)(ga + 8 * GSTR + 16);
            #pragma unroll
            for (int n = 0; n < 4; ++n) {
                uint32_t bf[2];
                const char* fa = smem + OFF_F + (ih * 32 + n * 8 + lr) * GSTR
                                 + kk * 32 + lm * 4;
                bf[0] = *(const uint32_t*)fa;
                bf[1] = *(const uint32_t*)(fa + 16);
                mma_f16(sacc[n], ag, bf);
            }
        }
        #pragma unroll
        for (int n = 0; n < 4; ++n) {
            const int ic = ih * 32 + n * 8 + lm * 2;
            float p0 = ex2f(sacc[n][0] * KSCALE);
            float p1 = ex2f(sacc[n][1] * KSCALE);
            float p2 = ex2f(sacc[n][2] * KSCALE);
            float p3 = ex2f(sacc[n][3] * KSCALE);
            lsum0 += p0 + p1;  lsum1 += p2 + p3;
            *(uint32_t*)(smem + OFF_P + (jw + lr) * VSTR + ic * 2)     = packh2(p0, p1);
            *(uint32_t*)(smem + OFF_P + (jw + lr + 8) * VSTR + ic * 2) = packh2(p2, p3);
        }
    }

    // ------------------------------ mainloop ------------------------------
    for (int t = 0; t < NIT; ++t) {
        const int cur = t & 1, nxt = (t + 1) & 1;
        __syncthreads();   // P(t)/V(t)/f(t+1) visible; old buffers free

        // loads: V(t+1) -> vbuf nxt, f(t+2) -> fbuf cur
        if (t + 1 < NIT) {
            const int i0n = (t + 1) * IT;
            #pragma unroll
            for (int it = 0; it < 4; ++it) {
                int id = tid + NTHR * it;
                int row = id >> 3, ch = id & 7;
                uint4 w = *reinterpret_cast<const uint4*>(&vB[(size_t)row * N_ + i0n + ch * 8]);
                *reinterpret_cast<uint4*>(smem + OFF_V + nxt * VBUF + row * VSTR + ch * 16) = w;
            }
            if (t + 2 < NIT && tid < 256) {
                const int i0n2 = (t + 2) * IT;
                int row = tid >> 2, ch = tid & 3;
                uint4 w = *reinterpret_cast<const uint4*>(
                    &fB[(size_t)(i0n2 + row) * CQ_ + ch * 8]);
                *reinterpret_cast<uint4*>(smem + OFF_F + cur * FBUF + row * GSTR + ch * 16) = w;
            }

            // ---- phase A(t+1): S(16j x 32i) -> P buf nxt ----
            float sacc[4][4] = {};
            #pragma unroll
            for (int kk = 0; kk < 2; ++kk) {
                uint32_t ag[4];
                const char* ga = smem + OFF_G + (jw + lr) * GSTR + kk * 32 + lm * 4;
                ag[0] = *(const uint32_t*)ga;
                ag[1] = *(const uint32_t*)(ga + 8 * GSTR);
                ag[2] = *(const uint32_t*)(ga + 16);
                ag[3] = *(const uint32_t*)(ga + 8 * GSTR + 16);
                #pragma unroll
                for (int n = 0; n < 4; ++n) {
                    uint32_t bf[2];
                    const char* fa = smem + OFF_F + nxt * FBUF
                                     + (ih * 32 + n * 8 + lr) * GSTR + kk * 32 + lm * 4;
                    bf[0] = *(const uint32_t*)fa;
                    bf[1] = *(const uint32_t*)(fa + 16);
                    mma_f16(sacc[n], ag, bf);
                }
            }
            #pragma unroll
            for (int n = 0; n < 4; ++n) {
                const int ic = ih * 32 + n * 8 + lm * 2;
                float p0 = ex2f(sacc[n][0] * KSCALE);
                float p1 = ex2f(sacc[n][1] * KSCALE);
                float p2 = ex2f(sacc[n][2] * KSCALE);
                float p3 = ex2f(sacc[n][3] * KSCALE);
                lsum0 += p0 + p1;  lsum1 += p2 + p3;
                *(uint32_t*)(smem + OFF_P + nxt * PBUF + (jw + lr) * VSTR + ic * 2)
                    = packh2(p0, p1);
                *(uint32_t*)(smem + OFF_P + nxt * PBUF + (jw + lr + 8) * VSTR + ic * 2)
                    = packh2(p2, p3);
            }
        }

        // ---- phase B(t): O(16c x 128j) += V(t) * P(t)  [bufs cur] ----
        #pragma unroll
        for (int kk = 0; kk < 4; ++kk) {          // i chunks of 16
            uint32_t af[4];
            const char* aa = smem + OFF_V + cur * VBUF + (cw + lr) * VSTR
                             + kk * 32 + lm * 4;
            af[0] = *(const uint32_t*)aa;
            af[1] = *(const uint32_t*)(aa + 8 * VSTR);
            af[2] = *(const uint32_t*)(aa + 16);
            af[3] = *(const uint32_t*)(aa + 8 * VSTR + 16);
            #pragma unroll
            for (int n = 0; n < 16; ++n) {        // j blocks of 8
                uint32_t bf[2];
                const char* ba = smem + OFF_P + cur * PBUF + (n * 8 + lr) * VSTR
                                 + kk * 32 + lm * 4;
                bf[0] = *(const uint32_t*)ba;
                bf[1] = *(const uint32_t*)(ba + 16);
                mma_f16(oacc[n], af, bf);
            }
        }
    }

    // ---- row sums -> rinv ----
    lsum0 += __shfl_xor_sync(0xffffffffu, lsum0, 1);
    lsum0 += __shfl_xor_sync(0xffffffffu, lsum0, 2);
    lsum1 += __shfl_xor_sync(0xffffffffu, lsum1, 1);
    lsum1 += __shfl_xor_sync(0xffffffffu, lsum1, 2);
    __syncthreads();
    if (lm == 0) {
        float* lred = reinterpret_cast<float*>(smem + OFF_LRED);
        lred[warp * 16 + lr]     = lsum0;
        lred[warp * 16 + lr + 8] = lsum1;
    }
    __syncthreads();
    if (tid < 128) {
        const float* lred = reinterpret_cast<const float*>(smem + OFF_LRED);
        int s = tid >> 4, jl = tid & 15;           // strip s = warps 2s, 2s+1
        reinterpret_cast<float*>(smem + OFF_RINV)[tid] =
            1.0f / (lred[(2 * s) * 16 + jl] + lred[(2 * s + 1) * 16 + jl]);
    }
    __syncthreads();
    const float* rinv = reinterpret_cast<const float*>(smem + OFF_RINV);

    // ---- write O ----
    #pragma unroll
    for (int n = 0; n < 16; ++n) {
        const int c = cw + lr;
        const int j = n * 8 + lm * 2;
        const float r0 = rinv[j], r1 = rinv[j + 1];
        float2 o0 = make_float2(oacc[n][0] * r0, oacc[n][1] * r1);
        float2 o1 = make_float2(oacc[n][2] * r0, oacc[n][3] * r1);
        *reinterpret_cast<float2*>(&out[((size_t)b * C_ + c) * N_ + jb + j])     = o0;
        *reinterpret_cast<float2*>(&out[((size_t)b * C_ + c + 8) * N_ + jb + j]) = o1;
    }
}

// ---------------------------------------------------------------------------
extern "C" void kernel_launch(void* const* d_in, const int* in_sizes, int n_in,
                              void* d_out, int out_size) {
    (void)in_sizes; (void)n_in; (void)out_size;
    const float* x  = (const float*)d_in[0];
    const float* Wq = (const float*)d_in[1];
    const float* Wk = (const float*)d_in[2];
    const float* Wv = (const float*)d_in[3];
    float* out = (float*)d_out;

    static int smem_set = 0;
    if (!smem_set) {
        cudaFuncSetAttribute(fused_attn_mma,
                             cudaFuncAttributeMaxDynamicSharedMemorySize, SMEM_TOTAL);
        smem_set = 1;
    }

    dim3 blk(256);
    // d_f (i / softmax side) takes Wq (query, f_ref);
    // d_g (j / output side)  takes Wk (key,   g_ref).
    proj_fg_kernel<<<dim3(N_ / 128, 1, B_), blk>>>(Wq, x, 0);   // Wq -> d_f
    proj_fg_kernel<<<dim3(N_ / 128, 1, B_), blk>>>(Wk, x, 1);   // Wk -> d_g
    proj_v_kernel<<<dim3(N_ / 128, C_ / 32, B_), blk>>>(Wv, x);
    fused_attn_mma<<<dim3(N_ / JT, B_), NTHR, SMEM_TOTAL>>>(out);
}

// round 10
// speedup vs baseline: 1.1125x; 1.1125x over previous
#include <cuda_runtime.h>
#include <cuda_fp16.h>
#include <cstdint>
#include <cstddef>

#define B_  4
#define C_  256
#define CQ_ 32
#define N_  4096
#define JT  128             // j tile per CTA
#define IT  128             // i tile per mainloop step
#define NIT (N_ / IT)       // 32
#define NTHR 512            // 16 warps
#define KSCALE 0.09016844005556021f   // (1/16) * log2(e)

// ---------------- scratch (device globals: allocation-free, 10 MB) ---------
// d_f: [b][n][q] Wq (query) projection -- the softmax/contraction index i side
// d_g: [b][n][q] Wk (key)   projection -- the output index j side
__device__ __half d_f[(size_t)B_ * N_ * CQ_];
__device__ __half d_g[(size_t)B_ * N_ * CQ_];
__device__ __half d_v[(size_t)B_ * C_ * N_];    // [b][c][n] values

__device__ __forceinline__ float ex2f(float x) {
    float y; asm("ex2.approx.f32 %0, %1;" : "=f"(y) : "f"(x)); return y;
}
__device__ __forceinline__ void mma_f16(float* d, const uint32_t* a,
                                        const uint32_t* b) {
    asm volatile(
        "mma.sync.aligned.m16n8k16.row.col.f32.f16.f16.f32 "
        "{%0,%1,%2,%3}, {%4,%5,%6,%7}, {%8,%9}, {%0,%1,%2,%3};"
        : "+f"(d[0]), "+f"(d[1]), "+f"(d[2]), "+f"(d[3])
        : "r"(a[0]), "r"(a[1]), "r"(a[2]), "r"(a[3]), "r"(b[0]), "r"(b[1]));
}
__device__ __forceinline__ uint32_t packh2(float a, float b) {
    __half2 p = __floats2half2_rn(a, b);
    return *reinterpret_cast<uint32_t*>(&p);
}

// --------------------------- SMEM layout (bytes) ---------------------------
// g/f tiles: [row][32 fp16], row stride 80 B (conflict-free frag loads)
// V tile:    [256 c][128 i fp16], row stride 272 B
// P tile:    [128 j][128 i fp16] k-interleaved, row stride 288 B:
//   within each 16-i group, column pair p (=0..7) stored at 4B slot
//   pos(p) = (p&3)*2 + (p>>2), so an 8B LDS.64 at slot 2*lm yields the
//   m16n8k16 B-fragment pair (k=2lm,2lm+1 | k=2lm+8,2lm+9) directly.
#define GSTR 80
#define VSTR 272
#define PSTR 288
#define OFF_G    0                       // 128*80   = 10240
#define OFF_F    10240                   // 128*80   = 10240
#define OFF_V    20480                   // 256*272  = 69632
#define OFF_P    90112                   // 128*288  = 36864
#define OFF_LRED 126976                  // 16*16*4 = 1024
#define OFF_RINV 128000                  // 128*4
#define SMEM_TOTAL 128512

// =================== kernel 1a: f/g projection (fp32 FFMA) ================
// Y[b][n][q] (fp16, transposed) = W[q][c] @ x[b][c][n]
__global__ void proj_fg_kernel(const float* __restrict__ W,
                               const float* __restrict__ x, int which) {
    __half* Y = which ? d_g : d_f;
    const int b  = blockIdx.z;
    const int n0 = blockIdx.x * 128;
    const float* X = x + (size_t)b * C_ * N_;

    __shared__ float Ws[32][33];
    __shared__ float Xs[32][128];

    const int tid = threadIdx.x;
    const int r0 = (tid >> 5) << 2;
    const int c0 = (tid & 31) << 2;

    float acc[4][4] = {};
    for (int kk = 0; kk < C_; kk += 32) {
        #pragma unroll
        for (int it = 0; it < 4; ++it) {
            int e = tid + 256 * it;
            int r = e >> 5, cc = e & 31;
            Ws[r][cc] = W[(size_t)r * C_ + kk + cc];
        }
        #pragma unroll
        for (int it = 0; it < 4; ++it) {
            int e = tid + 256 * it;
            int r = e >> 5, c4 = (e & 31) << 2;
            *reinterpret_cast<float4*>(&Xs[r][c4]) =
                *reinterpret_cast<const float4*>(&X[(size_t)(kk + r) * N_ + n0 + c4]);
        }
        __syncthreads();
        #pragma unroll
        for (int k = 0; k < 32; ++k) {
            float4 xv = *reinterpret_cast<const float4*>(&Xs[k][c0]);
            #pragma unroll
            for (int i = 0; i < 4; ++i) {
                float w = Ws[r0 + i][k];
                acc[i][0] = fmaf(w, xv.x, acc[i][0]);
                acc[i][1] = fmaf(w, xv.y, acc[i][1]);
                acc[i][2] = fmaf(w, xv.z, acc[i][2]);
                acc[i][3] = fmaf(w, xv.w, acc[i][3]);
            }
        }
        __syncthreads();
    }
    #pragma unroll
    for (int k = 0; k < 4; ++k) {   // transposed fp16 write: [n][q]
        int n = n0 + c0 + k;
        uint2 w2 = make_uint2(packh2(acc[0][k], acc[1][k]),
                              packh2(acc[2][k], acc[3][k]));
        *reinterpret_cast<uint2*>(&Y[((size_t)b * N_ + n) * CQ_ + r0]) = w2;
    }
}

// =================== kernel 1b: v projection (fp32 FFMA) ==================
__global__ void proj_v_kernel(const float* __restrict__ W,
                              const float* __restrict__ x) {
    const int b  = blockIdx.z;
    const int n0 = blockIdx.x * 128;
    const int m0 = blockIdx.y * 32;
    const float* X = x + (size_t)b * C_ * N_;

    __shared__ float Ws[32][33];
    __shared__ float Xs[32][128];

    const int tid = threadIdx.x;
    const int r0 = (tid >> 5) << 2;
    const int c0 = (tid & 31) << 2;

    float acc[4][4] = {};
    for (int kk = 0; kk < C_; kk += 32) {
        #pragma unroll
        for (int it = 0; it < 4; ++it) {
            int e = tid + 256 * it;
            int r = e >> 5, cc = e & 31;
            Ws[r][cc] = W[(size_t)(m0 + r) * C_ + kk + cc];
        }
        #pragma unroll
        for (int it = 0; it < 4; ++it) {
            int e = tid + 256 * it;
            int r = e >> 5, c4 = (e & 31) << 2;
            *reinterpret_cast<float4*>(&Xs[r][c4]) =
                *reinterpret_cast<const float4*>(&X[(size_t)(kk + r) * N_ + n0 + c4]);
        }
        __syncthreads();
        #pragma unroll
        for (int k = 0; k < 32; ++k) {
            float4 xv = *reinterpret_cast<const float4*>(&Xs[k][c0]);
            #pragma unroll
            for (int i = 0; i < 4; ++i) {
                float w = Ws[r0 + i][k];
                acc[i][0] = fmaf(w, xv.x, acc[i][0]);
                acc[i][1] = fmaf(w, xv.y, acc[i][1]);
                acc[i][2] = fmaf(w, xv.z, acc[i][2]);
                acc[i][3] = fmaf(w, xv.w, acc[i][3]);
            }
        }
        __syncthreads();
    }
    #pragma unroll
    for (int i = 0; i < 4; ++i) {
        uint2 w2 = make_uint2(packh2(acc[i][0], acc[i][1]),
                              packh2(acc[i][2], acc[i][3]));
        *reinterpret_cast<uint2*>(&d_v[((size_t)b * C_ + m0 + r0 + i) * N_ + n0 + c0]) = w2;
    }
}

// ============ kernel 2: fused scores+softmax+out via mma.sync =============
// Per CTA: batch b, 128-j tile. 16 warps, 512 threads.
//   Phase A: warps w=2s+h share j strip [16s,16s+16); h picks 64-i half.
//            S[j][i] = sum_q g[j][q] f[i][q]; p=ex2(S*KSCALE) -> fp16 P[j][i]
//            (k-interleaved layout).
//   Phase B: warp w=(4a+bq) owns c strip [64a,64a+64) x j block [32bq,32bq+32),
//            K=128/tile, fp32 accum (oacc[4][4][4]=64 regs) over 32 i-tiles.
//            Balanced 64x32 warp tile halves smem crossbar traffic vs 16x128.
__global__ void __launch_bounds__(NTHR, 1)
fused_attn_mma(float* __restrict__ out) {
    extern __shared__ __align__(16) char smem[];
    const int b  = blockIdx.y;
    const int jb = blockIdx.x * JT;
    const int tid  = threadIdx.x;
    const int lane = tid & 31, warp = tid >> 5;
    const int lr = lane >> 2, lm = lane & 3;
    const int jw = (warp >> 1) * 16;    // phase-A j strip (2 warps share)
    const int ih = warp & 1;            // phase-A i half (0: 0-63, 1: 64-127)
    const int ca = (warp >> 2) * 64;    // phase-B c block
    const int jq = (warp & 3) * 32;     // phase-B j block

    const __half* fB = d_f + (size_t)b * N_ * CQ_;
    const __half* gB = d_g + (size_t)b * N_ * CQ_;
    const __half* vB = d_v + (size_t)b * C_ * N_;

    // ---- g (key) tile once: [j][32 q] fp16, 64B data per 80B row ----
    {
        int row = tid >> 2, ch = tid & 3;              // 512 x 16B
        uint4 w = *reinterpret_cast<const uint4*>(&gB[(size_t)(jb + row) * CQ_ + ch * 8]);
        *reinterpret_cast<uint4*>(smem + OFF_G + row * GSTR + ch * 16) = w;
    }

    float oacc[4][4][4];
    #pragma unroll
    for (int m = 0; m < 4; ++m)
        #pragma unroll
        for (int n = 0; n < 4; ++n)
            #pragma unroll
            for (int k = 0; k < 4; ++k) oacc[m][n][k] = 0.f;
    float lsum0 = 0.f, lsum1 = 0.f;

    for (int t = 0; t < NIT; ++t) {
        const int i0 = t * IT;
        if (t > 0) __syncthreads();               // phase B done with P/V/f

        // f (query) tile: [i][32 q], 512 x 16B
        {
            int row = tid >> 2, ch = tid & 3;
            uint4 w = *reinterpret_cast<const uint4*>(&fB[(size_t)(i0 + row) * CQ_ + ch * 8]);
            *reinterpret_cast<uint4*>(smem + OFF_F + row * GSTR + ch * 16) = w;
        }
        // V tile: [256 c][128 i] fp16, 4096 x 16B
        #pragma unroll
        for (int it = 0; it < 8; ++it) {
            int id = tid + NTHR * it;
            int row = id >> 4, ch = id & 15;
            uint4 w = *reinterpret_cast<const uint4*>(&vB[(size_t)row * N_ + i0 + ch * 8]);
            *reinterpret_cast<uint4*>(smem + OFF_V + row * VSTR + ch * 16) = w;
        }
        __syncthreads();                          // tiles (and g at t=0) visible

        // ---------------- phase A: S strip (16 j x 64 i) + exp -> P -------
        {
            float sacc[8][4] = {};
            #pragma unroll
            for (int kk = 0; kk < 2; ++kk) {      // q chunks of 16
                uint32_t ag[4];
                const char* ga = smem + OFF_G + (jw + lr) * GSTR + kk * 32 + lm * 4;
                ag[0] = *(const uint32_t*)ga;
                ag[1] = *(const uint32_t*)(ga + 8 * GSTR);
                ag[2] = *(const uint32_t*)(ga + 16);
                ag[3] = *(const uint32_t*)(ga + 8 * GSTR + 16);
                #pragma unroll
                for (int n = 0; n < 8; ++n) {
                    uint32_t bf[2];
                    const char* fa = smem + OFF_F + (ih * 64 + n * 8 + lr) * GSTR
                                     + kk * 32 + lm * 4;
                    bf[0] = *(const uint32_t*)fa;
                    bf[1] = *(const uint32_t*)(fa + 16);
                    mma_f16(sacc[n], ag, bf);
                }
            }
            #pragma unroll
            for (int n = 0; n < 8; ++n) {
                // i columns 2lm, 2lm+1 of block ih*64 + n*8 -> permuted slot:
                // group gi = ih*4 + (n>>1), slot pos = 2*lm + (n&1)
                const int po = (ih * 4 + (n >> 1)) * 32 + (2 * lm + (n & 1)) * 4;
                float p0 = ex2f(sacc[n][0] * KSCALE);
                float p1 = ex2f(sacc[n][1] * KSCALE);
                float p2 = ex2f(sacc[n][2] * KSCALE);
                float p3 = ex2f(sacc[n][3] * KSCALE);
                lsum0 += p0 + p1;  lsum1 += p2 + p3;
                *(uint32_t*)(smem + OFF_P + (jw + lr) * PSTR + po)     = packh2(p0, p1);
                *(uint32_t*)(smem + OFF_P + (jw + lr + 8) * PSTR + po) = packh2(p2, p3);
            }
        }
        __syncthreads();                          // P visible

        // ---------------- phase B: O (64 c x 32 j) += V * P ---------------
        #pragma unroll
        for (int kk = 0; kk < 8; ++kk) {          // i chunks of 16
            uint32_t af[4][4];
            #pragma unroll
            for (int m = 0; m < 4; ++m) {
                const char* aa = smem + OFF_V + (ca + m * 16 + lr) * VSTR
                                 + kk * 32 + lm * 4;
                af[m][0] = *(const uint32_t*)aa;
                af[m][1] = *(const uint32_t*)(aa + 8 * VSTR);
                af[m][2] = *(const uint32_t*)(aa + 16);
                af[m][3] = *(const uint32_t*)(aa + 8 * VSTR + 16);
            }
            #pragma unroll
            for (int n = 0; n < 4; ++n) {
                uint2 bv = *(const uint2*)(smem + OFF_P + (jq + n * 8 + lr) * PSTR
                                           + kk * 32 + lm * 8);
                uint32_t bf[2] = { bv.x, bv.y };
                #pragma unroll
                for (int m = 0; m < 4; ++m)
                    mma_f16(oacc[m][n], af[m], bf);
            }
        }
    }

    // ---- row sums -> rinv ----
    lsum0 += __shfl_xor_sync(0xffffffffu, lsum0, 1);
    lsum0 += __shfl_xor_sync(0xffffffffu, lsum0, 2);
    lsum1 += __shfl_xor_sync(0xffffffffu, lsum1, 1);
    lsum1 += __shfl_xor_sync(0xffffffffu, lsum1, 2);
    __syncthreads();                               // phase B done reading P
    if (lm == 0) {
        float* lred = reinterpret_cast<float*>(smem + OFF_LRED);
        lred[warp * 16 + lr]     = lsum0;          // [warp][local row]
        lred[warp * 16 + lr + 8] = lsum1;
    }
    __syncthreads();
    if (tid < 128) {
        const float* lred = reinterpret_cast<const float*>(smem + OFF_LRED);
        int s = tid >> 4, jl = tid & 15;           // strip s = warps 2s, 2s+1
        reinterpret_cast<float*>(smem + OFF_RINV)[tid] =
            1.0f / (lred[(2 * s) * 16 + jl] + lred[(2 * s + 1) * 16 + jl]);
    }
    __syncthreads();
    const float* rinv = reinterpret_cast<const float*>(smem + OFF_RINV);

    // ---- write O ----
    #pragma unroll
    for (int m = 0; m < 4; ++m) {
        #pragma unroll
        for (int n = 0; n < 4; ++n) {
            const int c = ca + m * 16 + lr;
            const int j = jq + n * 8 + lm * 2;
            const float r0 = rinv[j], r1 = rinv[j + 1];
            float2 o0 = make_float2(oacc[m][n][0] * r0, oacc[m][n][1] * r1);
            float2 o1 = make_float2(oacc[m][n][2] * r0, oacc[m][n][3] * r1);
            *reinterpret_cast<float2*>(&out[((size_t)b * C_ + c) * N_ + jb + j])     = o0;
            *reinterpret_cast<float2*>(&out[((size_t)b * C_ + c + 8) * N_ + jb + j]) = o1;
        }
    }
}

// ---------------------------------------------------------------------------
extern "C" void kernel_launch(void* const* d_in, const int* in_sizes, int n_in,
                              void* d_out, int out_size) {
    (void)in_sizes; (void)n_in; (void)out_size;
    const float* x  = (const float*)d_in[0];
    const float* Wq = (const float*)d_in[1];
    const float* Wk = (const float*)d_in[2];
    const float* Wv = (const float*)d_in[3];
    float* out = (float*)d_out;

    static int smem_set = 0;
    if (!smem_set) {
        cudaFuncSetAttribute(fused_attn_mma,
                             cudaFuncAttributeMaxDynamicSharedMemorySize, SMEM_TOTAL);
        smem_set = 1;
    }

    dim3 blk(256);
    // d_f (i / softmax side) takes Wq (query, f_ref);
    // d_g (j / output side)  takes Wk (key,   g_ref).
    proj_fg_kernel<<<dim3(N_ / 128, 1, B_), blk>>>(Wq, x, 0);   // Wq -> d_f
    proj_fg_kernel<<<dim3(N_ / 128, 1, B_), blk>>>(Wk, x, 1);   // Wk -> d_g
    proj_v_kernel<<<dim3(N_ / 128, C_ / 32, B_), blk>>>(Wv, x);
    fused_attn_mma<<<dim3(N_ / JT, B_), NTHR, SMEM_TOTAL>>>(out);
}